// round 6
// baseline (speedup 1.0000x reference)
#include <cuda_runtime.h>

#define B 512
#define N 512
#define THREADS 256
#define NB 512
#define FULL 0xffffffffu
#define NGRP 16
#define GRP_SZ (B / NGRP)   // 32 CTAs per group

// Two-level cross-block accumulators (zero at load; finalizer resets for
// graph replay). Distinct addresses per group -> parallel L2 atomic lanes.
__device__ double             g_sum_part[NGRP];
__device__ unsigned long long g_pairs_part[NGRP];
__device__ unsigned int       g_done1[NGRP];
__device__ unsigned int       g_done2 = 0u;

// Monotone non-decreasing float -> bucket map. Clamped ends are safe: the
// query checks the threshold's own bucket exactly.
__device__ __forceinline__ int bucket_of(float q) {
    float f = (q + 8.0f) * 32.0f;
    f = fminf(fmaxf(f, 0.0f), 511.0f);
    return (int)f;                       // trunc == floor (f >= 0)
}

__global__ void __launch_bounds__(THREADS)
fused_kernel(const float* __restrict__ scores,
             const unsigned int* __restrict__ labels,
             float* __restrict__ out) {
    __shared__ int   s_cnt[NB];      // per-bucket neg count
    __shared__ float s_sum[NB];      // per-bucket neg sum
    __shared__ int   s_start[NB];    // excl suffix count = count(bucket > b) = seg start
    __shared__ float s_ssum[NB];     // excl suffix sum   = sum(bucket > b)
    __shared__ int   s_cur[NB];      // scatter cursors
    __shared__ float s_scat[N];      // negs, descending-bucket order
    __shared__ float s_pos[N];       // compacted positive scores
    __shared__ int   s_npos;
    __shared__ float s_gtc[16], s_gts[16];
    __shared__ float s_red[THREADS / 32];

    const int row  = blockIdx.x;
    const int tid  = threadIdx.x;
    const int lane = tid & 31;
    const int wrp  = tid >> 5;

    // ---- zero histograms + dtype detect (1 bar orders both)
    s_cnt[tid] = 0;  s_cnt[tid + 256] = 0;
    s_sum[tid] = 0.f; s_sum[tid + 256] = 0.f;
    if (tid == 0) s_npos = 0;
    const unsigned int probe = labels[2 * tid + 1];
    const int any_odd = __syncthreads_or(probe != 0u);        // bar 1
    const int stride = any_odd ? 1 : 2;

    const float*        srow = scores + (size_t)row * N;
    const unsigned int* lrow = labels + (size_t)row * N * stride;

    // ---- load + classify + histogram (keep negs in registers for scatter)
    float v[2]; int bk[2]; bool isneg[2];
    #pragma unroll
    for (int e = 0; e < 2; e++) {
        int i = tid + e * THREADS;
        float q = srow[i];
        unsigned int lab = lrow[(size_t)i * stride];
        v[e] = q;
        isneg[e] = (lab == 0u);
        if (isneg[e]) {
            int b = bucket_of(q);
            bk[e] = b;
            atomicAdd(&s_cnt[b], 1);
            atomicAdd(&s_sum[b], q);
        } else {
            bk[e] = 0;
            s_pos[atomicAdd(&s_npos, 1)] = q;
        }
    }
    __syncthreads();                                          // bar 2
    const int npos = s_npos;
    const int nneg = N - npos;

    // ---- suffix scan over 512 buckets: thread owns b0=tid, b1=tid+256.
    float c0 = (float)s_cnt[tid],       c1 = (float)s_cnt[tid + 256];
    float m0 = s_sum[tid],              m1 = s_sum[tid + 256];
    float ic0 = c0, ic1 = c1, is0 = m0, is1 = m1;
    #pragma unroll
    for (int o = 1; o < 32; o <<= 1) {
        float a = __shfl_down_sync(FULL, ic0, o);
        float b = __shfl_down_sync(FULL, is0, o);
        float c = __shfl_down_sync(FULL, ic1, o);
        float d = __shfl_down_sync(FULL, is1, o);
        if (lane + o < 32) { ic0 += a; is0 += b; ic1 += c; is1 += d; }
    }
    if (lane == 0) {                     // lane0 holds the full group total
        s_gtc[wrp]     = ic0;  s_gts[wrp]     = is0;
        s_gtc[8 + wrp] = ic1;  s_gts[8 + wrp] = is1;
    }
    __syncthreads();                                          // bar 3
    float oc0 = 0.f, os0 = 0.f, oc1 = 0.f, os1 = 0.f;
    for (int g = wrp + 1;     g < 16; g++) { oc0 += s_gtc[g]; os0 += s_gts[g]; }
    for (int g = 9 + wrp;     g < 16; g++) { oc1 += s_gtc[g]; os1 += s_gts[g]; }
    // exclusive suffix (strictly greater buckets); counts <= 512 exact in fp32
    int   ex0 = (int)(ic0 + oc0 - c0);
    int   ex1 = (int)(ic1 + oc1 - c1);
    s_start[tid]       = ex0;  s_ssum[tid]       = is0 + os0 - m0;
    s_start[tid + 256] = ex1;  s_ssum[tid + 256] = is1 + os1 - m1;
    s_cur[tid]       = ex0;
    s_cur[tid + 256] = ex1;
    __syncthreads();                                          // bar 4

    // ---- counting-sort scatter of negs (descending bucket order)
    #pragma unroll
    for (int e = 0; e < 2; e++) {
        if (isneg[e]) s_scat[atomicAdd(&s_cur[bk[e]], 1)] = v[e];
    }
    __syncthreads();                                          // bar 5

    // ---- per-pos query: base from suffix tables + exact in-bucket scan
    float acc = 0.0f;
    for (int pi = tid; pi < npos; pi += THREADS) {
        float p = s_pos[pi];
        float t = p - 1.0f;
        int b = bucket_of(t);
        float cg = (float)s_start[b];    // negs with bucket > b  =>  q > t
        float sg = s_ssum[b];
        int st = s_start[b];
        int en = st + s_cnt[b];
        for (int j = st; j < en; j++) {  // bucket b: exact comparison
            float q = s_scat[j];
            if (q > t) { cg += 1.0f; sg += q; }
        }
        acc += cg * (1.0f - p) + sg;
    }

    // ---- block reduce
    #pragma unroll
    for (int o = 16; o > 0; o >>= 1)
        acc += __shfl_down_sync(FULL, acc, o);
    if (lane == 0) s_red[wrp] = acc;
    __syncthreads();                                          // bar 6

    // ---- two-level cross-block accumulate + finalize
    if (tid == 0) {
        float vsum = 0.0f;
        #pragma unroll
        for (int w = 0; w < THREADS / 32; w++) vsum += s_red[w];

        const int grp = row >> 5;                   // 16 groups x 32 CTAs
        atomicAdd(&g_sum_part[grp], (double)vsum);  // distinct addr per group
        atomicAdd(&g_pairs_part[grp],
                  (unsigned long long)npos * (unsigned long long)nneg);
        __threadfence();                            // release partials
        unsigned int t1 = atomicAdd(&g_done1[grp], 1u);
        if (t1 == GRP_SZ - 1) {                     // last CTA of this group
            __threadfence();                        // release before level-2
            unsigned int t2 = atomicAdd(&g_done2, 1u);
            if (t2 == NGRP - 1) {                   // last group: finalize
                __threadfence();                    // acquire all partials
                double    s  = 0.0;
                long long np = 0;
                #pragma unroll
                for (int g = 0; g < NGRP; g++) {
                    s  += atomicAdd(&g_sum_part[g], 0.0);
                    np += (long long)atomicAdd(&g_pairs_part[g], 0ULL);
                }
                out[0] = (np > 0) ? (float)(s / (double)np) : 0.0f;
                // reset for next graph replay
                #pragma unroll
                for (int g = 0; g < NGRP; g++) {
                    g_sum_part[g]   = 0.0;
                    g_pairs_part[g] = 0ULL;
                    g_done1[g]      = 0u;
                }
                __threadfence();
                g_done2 = 0u;
            }
        }
    }
}

extern "C" void kernel_launch(void* const* d_in, const int* in_sizes, int n_in,
                              void* d_out, int out_size) {
    const float*        scores = (const float*)d_in[0];
    const unsigned int* labels = (const unsigned int*)d_in[1];
    float*              out    = (float*)d_out;

    fused_kernel<<<B, THREADS>>>(scores, labels, out);
}